// round 17
// baseline (speedup 1.0000x reference)
#include <cuda_runtime.h>
#include <cstdint>

// ---------------- shapes ----------------
#define BZ 64
#define LL 2048
#define DD 512
#define UU 512
#define AA 512
#define KK 64
#define VV 32000
#define EE 256
#define QW 7

#define HT_OFF  (BZ*VV)
#define ATTN_OFF (BZ*VV + BZ*UU)

#define EY_SPLIT 50
#define CTX_SPLIT 16

// ---------------- scratch ----------------
__device__ float g_Qext[32*512];
__device__ float g_ha[BZ*AA];
__device__ float g_logitpart[4*BZ*LL];
__device__ float g_logit[BZ*LL];
__device__ float g_ctxpart[CTX_SPLIT*BZ*DD];
__device__ float g_context[BZ*DD];
__device__ float g_eypart[EY_SPLIT*BZ*EE];
__device__ float g_Ey[BZ*EE];
__device__ float g_zt[BZ*UU];
__device__ float g_rt[BZ*UU];
__device__ float g_hpart[BZ*UU];
__device__ float g_ht[BZ*UU];
__device__ float g_oute[BZ*EE];
__device__ float g_vlogits[BZ*VV];

// ---------------- cp.async helpers ----------------
__device__ __forceinline__ void cp_async16(void* smem, const void* gmem) {
    unsigned sa = (unsigned)__cvta_generic_to_shared(smem);
    asm volatile("cp.async.cg.shared.global [%0], [%1], 16;" :: "r"(sa), "l"(gmem));
}
__device__ __forceinline__ void cp_commit() { asm volatile("cp.async.commit_group;"); }
template<int N> __device__ __forceinline__ void cp_wait() {
    asm volatile("cp.async.wait_group %0;" :: "n"(N));
}

// ---------------- merged prep: Qext | ha ----------------
__global__ void prep_all_kernel(const float* __restrict__ Qk, const float* __restrict__ Uf,
                                const float* __restrict__ h,  const float* __restrict__ Wa)
{
    __shared__ float hs[UU];
    int bx = blockIdx.x, t = threadIdx.x;
    if (bx < 64) {
        int i = bx*256 + t;
        int w = i >> 9, a = i & 511;
        float s = 0.f;
        if (w < QW)
            for (int k = 0; k < KK; k++) s = fmaf(Qk[w*KK + k], Uf[k*AA + a], s);
        g_Qext[i] = s;
    } else {
        int b = bx - 64;
        for (int i = t; i < UU; i += 256) hs[i] = h[b*UU + i];
        __syncthreads();
        float a0 = 0.f, a1 = 0.f;
        for (int k = 0; k < UU; k++) {
            float hv = hs[k];
            a0 = fmaf(hv, Wa[k*AA + t],       a0);
            a1 = fmaf(hv, Wa[k*AA + t + 256], a1);
        }
        g_ha[b*AA + t]       = a0;
        g_ha[b*AA + t + 256] = a1;
    }
}

// ---------------- tf32 mma ----------------
__device__ __forceinline__ void mma_tf32(float* c, const uint32_t* a, const uint32_t* b) {
    asm volatile(
        "mma.sync.aligned.m16n8k8.row.col.f32.tf32.tf32.f32 "
        "{%0,%1,%2,%3}, {%4,%5,%6,%7}, {%8,%9}, {%0,%1,%2,%3};"
        : "+f"(c[0]), "+f"(c[1]), "+f"(c[2]), "+f"(c[3])
        : "r"(a[0]), "r"(a[1]), "r"(a[2]), "r"(a[3]), "r"(b[0]), "r"(b[1]));
}
__device__ __forceinline__ float fast_tanh(float x) {
    x = fminf(fmaxf(x, -15.f), 15.f);
    float e = __expf(2.f * x);
    return (e - 1.f) / (e + 1.f);
}

// ---------------- attention logits: frozen R15 version ----------------
#define NCHUNK 17
#define STGF 8960
#define SM_HAS (3*STGF)
#define SM_VAS (SM_HAS+128)
#define SM_TOTF (SM_VAS+128)

__global__ __launch_bounds__(256, 2)
void attn_mma_kernel(const float* __restrict__ feat,
                     const float* __restrict__ Ua,
                     const float* __restrict__ Va,
                     const float* __restrict__ Bm)
{
    extern __shared__ float sm[];
    float* has = sm + SM_HAS;
    float* vas = sm + SM_VAS;

    int t = threadIdx.x;
    int lane = t & 31, wid = t >> 5;
    int wm = wid & 3, wn = wid >> 2;
    int qid = lane >> 2, tq = lane & 3;

    int b  = blockIdx.x >> 6;
    int l0 = ((blockIdx.x >> 2) & 15) << 7;
    int n0 = (blockIdx.x & 3) << 7;

    if (t < 128) { has[t] = g_ha[b*AA + n0 + t]; vas[t] = Va[n0 + t]; }

    const float* fb = feat + (size_t)(b*LL + l0) * DD;
    const float* Bb = Bm + b*LL;

    float acc[2][8][4];
#pragma unroll
    for (int i = 0; i < 2; i++)
#pragma unroll
        for (int j = 0; j < 8; j++)
#pragma unroll
            for (int r = 0; r < 4; r++) acc[i][j][r] = 0.f;

    auto issue = [&](int c) {
        int s = c % 3;
        float* As_ = sm + s*STGF;
        float* Bs_ = As_ + 4608;
        if (c < 16) {
            const float* Ap = fb + c*32;
            const float* Bp = Ua + (size_t)c*32*AA + n0;
#pragma unroll
            for (int r = 0; r < 4; r++) {
                int i = t + 256*r;
                int m = i >> 3, k4 = (i & 7) << 2;
                cp_async16(&As_[m*36 + k4], Ap + (size_t)m*DD + k4);
                int kr = i >> 5, n4 = (i & 31) << 2;
                cp_async16(&Bs_[kr*136 + n4], Bp + (size_t)kr*AA + n4);
            }
        } else {
#pragma unroll
            for (int r = 0; r < 16; r++) {
                int i = t + 256*r;
                int m = i >> 5, k = i & 31;
                float v = 0.f;
                if (k < QW) {
                    int ls = l0 + m + k - 3;
                    if (ls >= 0 && ls < LL) v = __ldg(&Bb[ls]);
                }
                As_[m*36 + k] = v;
            }
            const float* Bp = g_Qext + n0;
#pragma unroll
            for (int r = 0; r < 4; r++) {
                int i = t + 256*r;
                int kr = i >> 5, n4 = (i & 31) << 2;
                cp_async16(&Bs_[kr*136 + n4], Bp + (size_t)kr*AA + n4);
            }
        }
        cp_commit();
    };

    issue(0); issue(1);
    for (int c = 0; c < NCHUNK; c++) {
        if (c == NCHUNK-1) cp_wait<0>(); else cp_wait<1>();
        __syncthreads();
        if (c + 2 < NCHUNK) issue(c + 2);
        int s = c % 3;
        const float* As_ = sm + s*STGF;
        const float* Bs_ = As_ + 4608;
#pragma unroll
        for (int kk = 0; kk < 4; kk++) {
            uint32_t af[2][4], bf[8][2];
#pragma unroll
            for (int fm = 0; fm < 2; fm++) {
                int m0 = wm*32 + fm*16 + qid;
                af[fm][0] = __float_as_uint(As_[(m0    )*36 + kk*8 + tq    ]);
                af[fm][1] = __float_as_uint(As_[(m0 + 8)*36 + kk*8 + tq    ]);
                af[fm][2] = __float_as_uint(As_[(m0    )*36 + kk*8 + tq + 4]);
                af[fm][3] = __float_as_uint(As_[(m0 + 8)*36 + kk*8 + tq + 4]);
            }
#pragma unroll
            for (int fn = 0; fn < 8; fn++) {
                int nb = wn*64 + fn*8 + qid;
                bf[fn][0] = __float_as_uint(Bs_[(kk*8 + tq    )*136 + nb]);
                bf[fn][1] = __float_as_uint(Bs_[(kk*8 + tq + 4)*136 + nb]);
            }
#pragma unroll
            for (int fm = 0; fm < 2; fm++)
#pragma unroll
                for (int fn = 0; fn < 8; fn++)
                    mma_tf32(acc[fm][fn], af[fm], bf[fn]);
        }
    }

    float part[4] = {0.f, 0.f, 0.f, 0.f};
#pragma unroll
    for (int fm = 0; fm < 2; fm++)
#pragma unroll
        for (int fn = 0; fn < 8; fn++)
#pragma unroll
            for (int r = 0; r < 4; r++) {
                int half = r >> 1, j = r & 1;
                int nl = wn*64 + fn*8 + 2*tq + j;
                part[fm*2 + half] += fast_tanh(acc[fm][fn][r] + has[nl]) * vas[nl];
            }

    float* red = sm;
    __syncthreads();
#pragma unroll
    for (int p = 0; p < 4; p++) {
        int fm = p >> 1, half = p & 1;
        int rl = wm*32 + fm*16 + half*8 + qid;
        red[rl*9 + wn*4 + tq] = part[p];
    }
    __syncthreads();
    if (t < 128) {
        float s = 0.f;
#pragma unroll
        for (int x = 0; x < 8; x++) s += red[t*9 + x];
        g_logitpart[(size_t)(blockIdx.x & 3)*(BZ*LL) + b*LL + l0 + t] = s;
    }
}

// ---------------- gates3 (fp32) ----------------
__global__ void gates3_kernel(const float* __restrict__ Ey, const float* __restrict__ h,
                              const float* __restrict__ ctx,
                              const float* __restrict__ Wyz, const float* __restrict__ Uhz,
                              const float* __restrict__ Wccz,
                              const float* __restrict__ Wyr, const float* __restrict__ Uhr,
                              const float* __restrict__ Ccr,
                              const float* __restrict__ Wyh,
                              const float* __restrict__ b_wyh, const float* __restrict__ b_urh)
{
    __shared__ float As[64][33];
    __shared__ float Bs[32][64];
    int t = threadIdx.x;
    int tx = t & 15, ty = t >> 4;
    int n0 = blockIdx.x * 64;
    int gate = blockIdx.y;

    const float* Aps[3];
    const float* Bps[3];
    int Ks[3];
    float* C;
    if (gate == 0) {
        Aps[0]=Ey; Bps[0]=Wyz; Ks[0]=EE;
        Aps[1]=h;  Bps[1]=Uhz; Ks[1]=UU;
        Aps[2]=ctx;Bps[2]=Wccz;Ks[2]=DD;
        C = g_zt;
    } else if (gate == 1) {
        Aps[0]=Ey; Bps[0]=Wyr; Ks[0]=EE;
        Aps[1]=h;  Bps[1]=Uhr; Ks[1]=UU;
        Aps[2]=ctx;Bps[2]=Ccr; Ks[2]=DD;
        C = g_rt;
    } else {
        Aps[0]=Ey; Bps[0]=Wyh; Ks[0]=EE;
        Aps[1]=ctx;Bps[1]=Wccz;Ks[1]=DD;
        Aps[2]=nullptr; Bps[2]=nullptr; Ks[2]=0;
        C = g_hpart;
    }

    float acc[4][4];
#pragma unroll
    for (int i = 0; i < 4; i++)
#pragma unroll
        for (int j = 0; j < 4; j++) acc[i][j] = 0.f;

    for (int p = 0; p < 3; p++) {
        const float* A = Aps[p];
        if (A == nullptr) continue;
        const float* Bm = Bps[p];
        int K = Ks[p];
        float ar[8], br[8];
#pragma unroll
        for (int r = 0; r < 8; r++) {
            int e = t + 256*r;
            ar[r] = A[(e >> 5)*K + (e & 31)];
            br[r] = Bm[(size_t)(e >> 6)*UU + n0 + (e & 63)];
        }
        for (int kc = 0; kc < K; kc += 32) {
            __syncthreads();
#pragma unroll
            for (int r = 0; r < 8; r++) {
                int e = t + 256*r;
                As[e >> 5][e & 31] = ar[r];
                Bs[e >> 6][e & 63] = br[r];
            }
            __syncthreads();
            if (kc + 32 < K) {
#pragma unroll
                for (int r = 0; r < 8; r++) {
                    int e = t + 256*r;
                    ar[r] = A[(e >> 5)*K + kc + 32 + (e & 31)];
                    br[r] = Bm[(size_t)(kc + 32 + (e >> 6))*UU + n0 + (e & 63)];
                }
            }
#pragma unroll
            for (int k = 0; k < 32; k++) {
                float a[4];
#pragma unroll
                for (int i = 0; i < 4; i++) a[i] = As[ty*4 + i][k];
                float4 bv = *(const float4*)&Bs[k][tx*4];
                float bj[4] = {bv.x, bv.y, bv.z, bv.w};
#pragma unroll
                for (int i = 0; i < 4; i++)
#pragma unroll
                    for (int j = 0; j < 4; j++) acc[i][j] = fmaf(a[i], bj[j], acc[i][j]);
            }
        }
    }
#pragma unroll
    for (int i = 0; i < 4; i++) {
        int m = ty*4 + i;
#pragma unroll
        for (int j = 0; j < 4; j++) {
            int n = n0 + tx*4 + j;
            float v = acc[i][j];
            if (gate < 2) v = 1.f / (1.f + __expf(-v));
            else          v += b_wyh[n] + b_urh[n];
            C[m*UU + n] = v;
        }
    }
}

// ---------------- hcand finish + ht (fp32) ----------------
__global__ void hcand_ht_kernel(const float* __restrict__ h,
                                const float* __restrict__ Urh,
                                float* __restrict__ out_ht)
{
    __shared__ float As[64][33];
    __shared__ float Bs[32][64];
    int t = threadIdx.x;
    int tx = t & 15, ty = t >> 4;
    int n0 = blockIdx.x * 64;

    float acc[4][4];
#pragma unroll
    for (int i = 0; i < 4; i++)
#pragma unroll
        for (int j = 0; j < 4; j++) acc[i][j] = 0.f;

    float ar[8], br[8];
#pragma unroll
    for (int r = 0; r < 8; r++) {
        int e = t + 256*r;
        int m = e >> 5, k = e & 31;
        ar[r] = h[m*UU + k] * g_rt[m*UU + k];
        br[r] = Urh[(size_t)(e >> 6)*UU + n0 + (e & 63)];
    }
    for (int kc = 0; kc < UU; kc += 32) {
        __syncthreads();
#pragma unroll
        for (int r = 0; r < 8; r++) {
            int e = t + 256*r;
            As[e >> 5][e & 31] = ar[r];
            Bs[e >> 6][e & 63] = br[r];
        }
        __syncthreads();
        if (kc + 32 < UU) {
#pragma unroll
            for (int r = 0; r < 8; r++) {
                int e = t + 256*r;
                int m = e >> 5, k = kc + 32 + (e & 31);
                ar[r] = h[m*UU + k] * g_rt[m*UU + k];
                br[r] = Urh[(size_t)(kc + 32 + (e >> 6))*UU + n0 + (e & 63)];
            }
        }
#pragma unroll
        for (int k = 0; k < 32; k++) {
            float a[4];
#pragma unroll
            for (int i = 0; i < 4; i++) a[i] = As[ty*4 + i][k];
            float4 bv = *(const float4*)&Bs[k][tx*4];
            float bj[4] = {bv.x, bv.y, bv.z, bv.w};
#pragma unroll
            for (int i = 0; i < 4; i++)
#pragma unroll
                for (int j = 0; j < 4; j++) acc[i][j] = fmaf(a[i], bj[j], acc[i][j]);
        }
    }
#pragma unroll
    for (int i = 0; i < 4; i++) {
        int m = ty*4 + i;
#pragma unroll
        for (int j = 0; j < 4; j++) {
            int n = n0 + tx*4 + j;
            float hc = tanhf(acc[i][j] + g_hpart[m*UU + n]);
            float z  = g_zt[m*UU + n];
            float v  = (1.f - z) * h[m*UU + n] + z * hc;
            g_ht[m*UU + n] = v;
            out_ht[m*UU + n] = v;
        }
    }
}

// ---------------- generic small tf32 GEMM (oute only) ----------------
#define VG_STGF (2304 + 4352)
__global__ __launch_bounds__(256)
void small3_mma_kernel(const float* __restrict__ A0, int lda0, const float* __restrict__ B0, int ldb0, int K0,
                       const float* __restrict__ A1, int lda1, const float* __restrict__ B1, int ldb1, int K1,
                       const float* __restrict__ addm,
                       float* __restrict__ C, int ldc)
{
    extern __shared__ float sm[];
    int t = threadIdx.x;
    int lane = t & 31, wid = t >> 5;
    int qid = lane >> 2, tq = lane & 3;
    int n0 = blockIdx.x << 7;

    int c0 = K0 >> 5, c1 = K1 >> 5;
    int nchunk = c0 + c1;

    float acc[4][2][4];
#pragma unroll
    for (int i = 0; i < 4; i++)
#pragma unroll
        for (int j = 0; j < 2; j++)
#pragma unroll
            for (int r = 0; r < 4; r++) acc[i][j][r] = 0.f;

    auto issue = [&](int c) {
        float* As_ = sm + (c % 3)*VG_STGF;
        float* Bs_ = As_ + 2304;
        const float* Ap; int lda; const float* Bp; int ldb;
        int koff;
        if (c < c0) { Ap = A0; lda = lda0; Bp = B0; ldb = ldb0; koff = c*32; }
        else        { Ap = A1; lda = lda1; Bp = B1; ldb = ldb1; koff = (c - c0)*32; }
#pragma unroll
        for (int r = 0; r < 2; r++) {
            int i = t + 256*r;
            int m = i >> 3, k4 = (i & 7) << 2;
            cp_async16(&As_[m*36 + k4], Ap + (size_t)m*lda + koff + k4);
        }
#pragma unroll
        for (int r = 0; r < 4; r++) {
            int i = t + 256*r;
            int kr = i >> 5, n4 = (i & 31) << 2;
            cp_async16(&Bs_[kr*136 + n4], Bp + (size_t)(koff + kr)*ldb + n0 + n4);
        }
        cp_commit();
    };

    issue(0);
    if (nchunk > 1) issue(1);
    for (int c = 0; c < nchunk; c++) {
        if (c == nchunk-1) cp_wait<0>(); else cp_wait<1>();
        __syncthreads();
        if (c + 2 < nchunk) issue(c + 2);
        const float* As_ = sm + (c % 3)*VG_STGF;
        const float* Bs_ = As_ + 2304;
#pragma unroll
        for (int kk = 0; kk < 4; kk++) {
            uint32_t af[4][4], bf[2][2];
#pragma unroll
            for (int fm = 0; fm < 4; fm++) {
                int m0 = fm*16 + qid;
                af[fm][0] = __float_as_uint(As_[(m0    )*36 + kk*8 + tq    ]);
                af[fm][1] = __float_as_uint(As_[(m0 + 8)*36 + kk*8 + tq    ]);
                af[fm][2] = __float_as_uint(As_[(m0    )*36 + kk*8 + tq + 4]);
                af[fm][3] = __float_as_uint(As_[(m0 + 8)*36 + kk*8 + tq + 4]);
            }
#pragma unroll
            for (int fn = 0; fn < 2; fn++) {
                int nb = wid*16 + fn*8 + qid;
                bf[fn][0] = __float_as_uint(Bs_[(kk*8 + tq    )*136 + nb]);
                bf[fn][1] = __float_as_uint(Bs_[(kk*8 + tq + 4)*136 + nb]);
            }
#pragma unroll
            for (int fm = 0; fm < 4; fm++)
#pragma unroll
                for (int fn = 0; fn < 2; fn++)
                    mma_tf32(acc[fm][fn], af[fm], bf[fn]);
        }
        __syncthreads();
    }

#pragma unroll
    for (int fm = 0; fm < 4; fm++)
#pragma unroll
        for (int fn = 0; fn < 2; fn++)
#pragma unroll
            for (int r = 0; r < 4; r++) {
                int m = fm*16 + (r >> 1)*8 + qid;
                int n = n0 + wid*16 + fn*8 + 2*tq + (r & 1);
                C[m*ldc + n] = acc[fm][fn][r] + addm[m*ldc + n];
            }
}

// ---------------- vlogits: tf32 MMA, 3-stage ----------------
__global__ __launch_bounds__(256)
void vgemm_mma_kernel(const float* __restrict__ Aee, const float* __restrict__ Wo)
{
    extern __shared__ float sm[];
    int t = threadIdx.x;
    int lane = t & 31, wid = t >> 5;
    int qid = lane >> 2, tq = lane & 3;
    int n0 = blockIdx.x << 7;

    float acc[4][2][4];
#pragma unroll
    for (int i = 0; i < 4; i++)
#pragma unroll
        for (int j = 0; j < 2; j++)
#pragma unroll
            for (int r = 0; r < 4; r++) acc[i][j][r] = 0.f;

    auto issue = [&](int c) {
        float* As_ = sm + (c % 3)*VG_STGF;
        float* Bs_ = As_ + 2304;
#pragma unroll
        for (int r = 0; r < 2; r++) {
            int i = t + 256*r;
            int m = i >> 3, k4 = (i & 7) << 2;
            cp_async16(&As_[m*36 + k4], Aee + (size_t)m*EE + c*32 + k4);
        }
#pragma unroll
        for (int r = 0; r < 4; r++) {
            int i = t + 256*r;
            int kr = i >> 5, n4 = (i & 31) << 2;
            cp_async16(&Bs_[kr*136 + n4], Wo + (size_t)(c*32 + kr)*VV + n0 + n4);
        }
        cp_commit();
    };

    issue(0); issue(1);
    for (int c = 0; c < 8; c++) {
        if (c == 7) cp_wait<0>(); else cp_wait<1>();
        __syncthreads();
        if (c + 2 < 8) issue(c + 2);
        const float* As_ = sm + (c % 3)*VG_STGF;
        const float* Bs_ = As_ + 2304;
#pragma unroll
        for (int kk = 0; kk < 4; kk++) {
            uint32_t af[4][4], bf[2][2];
#pragma unroll
            for (int fm = 0; fm < 4; fm++) {
                int m0 = fm*16 + qid;
                af[fm][0] = __float_as_uint(As_[(m0    )*36 + kk*8 + tq    ]);
                af[fm][1] = __float_as_uint(As_[(m0 + 8)*36 + kk*8 + tq    ]);
                af[fm][2] = __float_as_uint(As_[(m0    )*36 + kk*8 + tq + 4]);
                af[fm][3] = __float_as_uint(As_[(m0 + 8)*36 + kk*8 + tq + 4]);
            }
#pragma unroll
            for (int fn = 0; fn < 2; fn++) {
                int nb = wid*16 + fn*8 + qid;
                bf[fn][0] = __float_as_uint(Bs_[(kk*8 + tq    )*136 + nb]);
                bf[fn][1] = __float_as_uint(Bs_[(kk*8 + tq + 4)*136 + nb]);
            }
#pragma unroll
            for (int fm = 0; fm < 4; fm++)
#pragma unroll
                for (int fn = 0; fn < 2; fn++)
                    mma_tf32(acc[fm][fn], af[fm], bf[fn]);
        }
    }

#pragma unroll
    for (int fm = 0; fm < 4; fm++)
#pragma unroll
        for (int fn = 0; fn < 2; fn++)
#pragma unroll
            for (int r = 0; r < 4; r++) {
                int m = fm*16 + (r >> 1)*8 + qid;
                int n = n0 + wid*16 + fn*8 + 2*tq + (r & 1);
                g_vlogits[(size_t)m*VV + n] = acc[fm][fn][r];
            }
}

// ---------------- Ey: tf32 MMA split-K, grid (2 n-tiles, 50 k-chunks of 640) ----------------
__global__ __launch_bounds__(256)
void ey_mma_kernel(const float* __restrict__ pt, const float* __restrict__ We)
{
    extern __shared__ float sm[];
    int t = threadIdx.x;
    int lane = t & 31, wid = t >> 5;
    int qid = lane >> 2, tq = lane & 3;
    int n0 = blockIdx.x << 7;
    int k0 = blockIdx.y * 640;

    float acc[4][2][4];
#pragma unroll
    for (int i = 0; i < 4; i++)
#pragma unroll
        for (int j = 0; j < 2; j++)
#pragma unroll
            for (int r = 0; r < 4; r++) acc[i][j][r] = 0.f;

    auto issue = [&](int c) {
        float* As_ = sm + (c % 3)*VG_STGF;
        float* Bs_ = As_ + 2304;
#pragma unroll
        for (int r = 0; r < 2; r++) {
            int i = t + 256*r;
            int m = i >> 3, k4 = (i & 7) << 2;
            cp_async16(&As_[m*36 + k4], pt + (size_t)m*VV + k0 + c*32 + k4);
        }
#pragma unroll
        for (int r = 0; r < 4; r++) {
            int i = t + 256*r;
            int kr = i >> 5, n4 = (i & 31) << 2;
            cp_async16(&Bs_[kr*136 + n4], We + (size_t)(k0 + c*32 + kr)*EE + n0 + n4);
        }
        cp_commit();
    };

    issue(0); issue(1);
    for (int c = 0; c < 20; c++) {
        if (c == 19) cp_wait<0>(); else cp_wait<1>();
        __syncthreads();
        if (c + 2 < 20) issue(c + 2);
        const float* As_ = sm + (c % 3)*VG_STGF;
        const float* Bs_ = As_ + 2304;
#pragma unroll
        for (int kk = 0; kk < 4; kk++) {
            uint32_t af[4][4], bf[2][2];
#pragma unroll
            for (int fm = 0; fm < 4; fm++) {
                int m0 = fm*16 + qid;
                af[fm][0] = __float_as_uint(As_[(m0    )*36 + kk*8 + tq    ]);
                af[fm][1] = __float_as_uint(As_[(m0 + 8)*36 + kk*8 + tq    ]);
                af[fm][2] = __float_as_uint(As_[(m0    )*36 + kk*8 + tq + 4]);
                af[fm][3] = __float_as_uint(As_[(m0 + 8)*36 + kk*8 + tq + 4]);
            }
#pragma unroll
            for (int fn = 0; fn < 2; fn++) {
                int nb = wid*16 + fn*8 + qid;
                bf[fn][0] = __float_as_uint(Bs_[(kk*8 + tq    )*136 + nb]);
                bf[fn][1] = __float_as_uint(Bs_[(kk*8 + tq + 4)*136 + nb]);
            }
#pragma unroll
            for (int fm = 0; fm < 4; fm++)
#pragma unroll
                for (int fn = 0; fn < 2; fn++)
                    mma_tf32(acc[fm][fn], af[fm], bf[fn]);
        }
        __syncthreads();
    }

    float* outp = g_eypart + (size_t)blockIdx.y*(BZ*EE);
#pragma unroll
    for (int fm = 0; fm < 4; fm++)
#pragma unroll
        for (int fn = 0; fn < 2; fn++)
#pragma unroll
            for (int r = 0; r < 4; r++) {
                int m = fm*16 + (r >> 1)*8 + qid;
                int n = n0 + wid*16 + fn*8 + 2*tq + (r & 1);
                outp[m*EE + n] = acc[fm][fn][r];
            }
}

// ---------------- combined reduce: ctx (blocks 0..127) | ey float4 (blocks 128..143) ----------------
__global__ void reduce2_kernel() {
    int bx = blockIdx.x, t = threadIdx.x;
    if (bx < 128) {
        int i = bx*256 + t;              // BZ*DD = 32768
        float s = 0.f;
#pragma unroll
        for (int lc = 0; lc < CTX_SPLIT; lc++) s += g_ctxpart[lc*(BZ*DD) + i];
        g_context[i] = s;
    } else {
        int i = (bx - 128)*256 + t;      // float4 index, BZ*EE/4 = 4096
        const float4* ep = (const float4*)g_eypart;
        float4 s = make_float4(0.f, 0.f, 0.f, 0.f);
#pragma unroll 5
        for (int kc = 0; kc < EY_SPLIT; kc++) {
            float4 v = ep[(size_t)kc*(BZ*EE/4) + i];
            s.x += v.x; s.y += v.y; s.z += v.z; s.w += v.w;
        }
        ((float4*)g_Ey)[i] = s;
    }
}

// ---------------- softmax over L ----------------
__global__ void softmaxL_kernel(float* __restrict__ attn) {
    int b = blockIdx.x, t = threadIdx.x;
    __shared__ float sred[256];
    const float* p0 = g_logitpart + 0*(BZ*LL) + b*LL;
    const float* p1 = g_logitpart + 1*(BZ*LL) + b*LL;
    const float* p2 = g_logitpart + 2*(BZ*LL) + b*LL;
    const float* p3 = g_logitpart + 3*(BZ*LL) + b*LL;
    float* lg = g_logit + b*LL;

    float mx = -1e30f;
    for (int l = t; l < LL; l += 256) {
        float v = p0[l] + p1[l] + p2[l] + p3[l];
        lg[l] = v;
        mx = fmaxf(mx, v);
    }
    sred[t] = mx; __syncthreads();
    for (int s = 128; s > 0; s >>= 1) { if (t < s) sred[t] = fmaxf(sred[t], sred[t+s]); __syncthreads(); }
    mx = sred[0]; __syncthreads();
    float sum = 0.f;
    for (int l = t; l < LL; l += 256) sum += __expf(lg[l] - mx);
    sred[t] = sum; __syncthreads();
    for (int s = 128; s > 0; s >>= 1) { if (t < s) sred[t] += sred[t+s]; __syncthreads(); }
    sum = sred[0]; __syncthreads();
    float inv = 1.f / sum;
    for (int l = t; l < LL; l += 256) attn[b*LL + l] = __expf(lg[l] - mx) * inv;
}

// ---------------- context (float4 loads) ----------------
__global__ void ctx_part_kernel(const float* __restrict__ feat, const float* __restrict__ attn) {
    int b = blockIdx.x >> 4, lc = blockIdx.x & 15;
    int t = threadIdx.x;
    int d4 = t << 2;
    const float* fb = feat + (size_t)(b*LL + lc*128) * DD;
    const float* ab = attn + b*LL + lc*128;
    float4 acc = make_float4(0.f, 0.f, 0.f, 0.f);
#pragma unroll 8
    for (int l = 0; l < 128; l++) {
        float w = ab[l];
        float4 f = *(const float4*)&fb[(size_t)l*DD + d4];
        acc.x = fmaf(w, f.x, acc.x);
        acc.y = fmaf(w, f.y, acc.y);
        acc.z = fmaf(w, f.z, acc.z);
        acc.w = fmaf(w, f.w, acc.w);
    }
    *(float4*)&g_ctxpart[lc*(BZ*DD) + b*DD + d4] = acc;
}

// ---------------- softmax over V (smem-cached) ----------------
__global__ void softmaxV_kernel(float* __restrict__ out) {
    extern __shared__ float row[];
    int b = blockIdx.x, t = threadIdx.x;
    __shared__ float sred[1024];
    const float4* lg4 = (const float4*)(g_vlogits + (size_t)b*VV);

    float mx = -1e30f;
    for (int i = t; i < VV/4; i += 1024) {
        float4 v = lg4[i];
        *(float4*)&row[i*4] = v;
        mx = fmaxf(fmaxf(mx, v.x), fmaxf(v.y, fmaxf(v.z, v.w)));
    }
    sred[t] = mx; __syncthreads();
    for (int s = 512; s > 0; s >>= 1) { if (t < s) sred[t] = fmaxf(sred[t], sred[t+s]); __syncthreads(); }
    mx = sred[0]; __syncthreads();

    float sum = 0.f;
    for (int v = t; v < VV; v += 1024) sum += __expf(row[v] - mx);
    sred[t] = sum; __syncthreads();
    for (int s = 512; s > 0; s >>= 1) { if (t < s) sred[t] += sred[t+s]; __syncthreads(); }
    sum = sred[0]; __syncthreads();

    float inv = 1.f / sum;
    float4* o4 = (float4*)(out + (size_t)b*VV);
    for (int i = t; i < VV/4; i += 1024) {
        float4 v = *(float4*)&row[i*4];
        v.x = __expf(v.x - mx) * inv;
        v.y = __expf(v.y - mx) * inv;
        v.z = __expf(v.z - mx) * inv;
        v.w = __expf(v.w - mx) * inv;
        o4[i] = v;
    }
}

// ---------------- launch ----------------
extern "C" void kernel_launch(void* const* d_in, const int* in_sizes, int n_in,
                              void* d_out, int out_size)
{
    const float* prev_target = (const float*)d_in[0];
    const float* prev_hidden = (const float*)d_in[1];
    const float* features    = (const float*)d_in[2];
    const float* Bmat        = (const float*)d_in[3];
    const float* Wa          = (const float*)d_in[4];
    const float* Ua          = (const float*)d_in[5];
    const float* Va          = (const float*)d_in[6];
    const float* Uf          = (const float*)d_in[7];
    const float* Qk          = (const float*)d_in[8];
    const float* We          = (const float*)d_in[9];
    const float* Wccz        = (const float*)d_in[10];
    const float* Wyz         = (const float*)d_in[11];
    const float* Uhz         = (const float*)d_in[12];
    const float* Wyr         = (const float*)d_in[13];
    const float* Uhr         = (const float*)d_in[14];
    const float* Ccr         = (const float*)d_in[15];
    const float* Wyh         = (const float*)d_in[16];
    const float* b_wyh       = (const float*)d_in[17];
    const float* Urh         = (const float*)d_in[18];
    const float* b_urh       = (const float*)d_in[19];
    const float* Wo          = (const float*)d_in[20];
    const float* Wh          = (const float*)d_in[21];
    const float* Wc          = (const float*)d_in[22];

    float* out      = (float*)d_out;
    float* out_ht   = (float*)d_out + HT_OFF;
    float* out_attn = (float*)d_out + ATTN_OFF;

    float* pctx;  cudaGetSymbolAddress((void**)&pctx, g_context);
    float* pEy;   cudaGetSymbolAddress((void**)&pEy, g_Ey);
    float* pht;   cudaGetSymbolAddress((void**)&pht, g_ht);
    float* poute; cudaGetSymbolAddress((void**)&poute, g_oute);

    cudaFuncSetAttribute(attn_mma_kernel, cudaFuncAttributeMaxDynamicSharedMemorySize, SM_TOTF*4);
    cudaFuncSetAttribute(vgemm_mma_kernel, cudaFuncAttributeMaxDynamicSharedMemorySize, 3*VG_STGF*4);
    cudaFuncSetAttribute(ey_mma_kernel, cudaFuncAttributeMaxDynamicSharedMemorySize, 3*VG_STGF*4);
    cudaFuncSetAttribute(small3_mma_kernel, cudaFuncAttributeMaxDynamicSharedMemorySize, 3*VG_STGF*4);
    cudaFuncSetAttribute(softmaxV_kernel, cudaFuncAttributeMaxDynamicSharedMemorySize, VV*4);

    // 1. prep (Qext | ha)
    prep_all_kernel<<<128, 256>>>(Qk, Uf, prev_hidden, Wa);

    // 2. Ey partials (independent branch)
    { dim3 g(2, EY_SPLIT); ey_mma_kernel<<<g, 256, 3*VG_STGF*4>>>(prev_target, We); }

    // 3. attention logits
    attn_mma_kernel<<<BZ*16*4, 256, SM_TOTF*4>>>(features, Ua, Va, Bmat);

    // 4. softmax over L
    softmaxL_kernel<<<BZ, 256>>>(out_attn);

    // 5. context partials
    ctx_part_kernel<<<BZ*CTX_SPLIT, 128>>>(features, out_attn);

    // 6. combined reduce (ctx + Ey)
    reduce2_kernel<<<144, 256>>>();

    // 7. zt | rt | hpart (fp32)
    { dim3 g(UU/64, 3); gates3_kernel<<<g, 256>>>(pEy, prev_hidden, pctx,
                                                  Wyz, Uhz, Wccz, Wyr, Uhr, Ccr,
                                                  Wyh, b_wyh, b_urh); }

    // 8. hcand finish + ht (fp32)
    hcand_ht_kernel<<<UU/64, 256>>>(prev_hidden, Urh, out_ht);

    // 9. oute = Ey + ht@Wh + ctx@Wc (tf32)
    small3_mma_kernel<<<EE/128, 256, 3*VG_STGF*4>>>(
        pht, UU, Wh, EE, UU,
        pctx, DD, Wc, EE, DD,
        pEy, poute, EE);

    // 10. vlogits = oute @ Wo
    vgemm_mma_kernel<<<VV/128, 256, 3*VG_STGF*4>>>(poute, Wo);

    // 11. softmax over V
    softmaxV_kernel<<<BZ, 1024, VV*4>>>(out);
}